// round 16
// baseline (speedup 1.0000x reference)
#include <cuda_runtime.h>
#include <cstdint>

// ---------------- Problem constants ----------------
#define NNODE   17
#define CIN     256
#define COUT    256
#define TB      8
#define BM      136                  // TB * NNODE rows per CTA
#define BMP     144
#define NTHR    768                  // 24 warps: 3 (M) x 8 (N)
#define KC      32                   // K per chunk
#define NCHUNK  8                    // 256 / 32
#define NSTAGE  3                    // cp.async pipeline depth
#define LDT     36                   // tile row stride (floats): conflict-free ldmatrix
#define LDGS    264                  // gs row stride (floats)

// ---------------- SMEM layout (bytes) ----------------
#define A_OFF   0
#define A_TILE  (BMP * LDT * 4)             // 20736
#define B_OFF   (NSTAGE * A_TILE)           // 62208
#define B_TILE  (256 * LDT * 4)             // 36864  (tiles end at 172800)
#define GS_OFF  0                           // epilogue overlay [144][264] = 152064
#define MST_OFF 172800                      // M transposed [128 cols][17] = 8704
#define AS_OFF  181504                      // 289 floats (+pad)
#define BS_OFF  182672                      // 128 floats
#define SMEM_TOTAL 183184

__device__ __align__(16) float g_Wt[512 * 256];   // [n][k] tf32-rounded; n = mat*256 + d
__device__ float g_Asym[NNODE * NNODE];

__device__ __forceinline__ uint32_t smem_u32(const void* p) {
    uint32_t a;
    asm("{ .reg .u64 t; cvta.to.shared.u64 t, %1; cvt.u32.u64 %0, t; }" : "=r"(a) : "l"(p));
    return a;
}

#define CP16(dst, src) asm volatile("cp.async.cg.shared.global [%0], [%1], 16;" \
    :: "r"(dst), "l"(__cvta_generic_to_global(src)))

#define LDSM4(r, addr) asm volatile( \
    "ldmatrix.sync.aligned.m8n8.x4.shared.b16 {%0,%1,%2,%3}, [%4];" \
    : "=r"((r)[0]), "=r"((r)[1]), "=r"((r)[2]), "=r"((r)[3]) : "r"(addr))

#define MMA_TF32(c, a, b0, b1) asm volatile( \
    "mma.sync.aligned.m16n8k8.row.col.f32.tf32.tf32.f32 " \
    "{%0,%1,%2,%3}, {%4,%5,%6,%7}, {%8,%9}, {%0,%1,%2,%3};" \
    : "+f"((c)[0]), "+f"((c)[1]), "+f"((c)[2]), "+f"((c)[3]) \
    : "r"((a)[0]), "r"((a)[1]), "r"((a)[2]), "r"((a)[3]), "r"(b0), "r"(b1))

__device__ __forceinline__ uint32_t to_tf32(float f) {
    unsigned u; asm("cvt.rna.tf32.f32 %0, %1;" : "=r"(u) : "f"(f));
    return u;
}

// -------- prep: W -> [n][k] transposed + tf32-rounded; symmetrize A --------
__global__ void mgc_prep(const float* __restrict__ W, const float* __restrict__ adj,
                         const float* __restrict__ adj2) {
    int e = blockIdx.x * 256 + threadIdx.x;
    if (e < 512 * 256) {
        int n = e >> 8, k = e & 255;
        int mat = n >> 8, d = n & 255;
        g_Wt[e] = __uint_as_float(to_tf32(W[mat * (CIN * COUT) + k * COUT + d]));
    }
    if (blockIdx.x == 0) {
        for (int t = threadIdx.x; t < NNODE * NNODE; t += 256) {
            int i = t / NNODE, j = t % NNODE;
            float a = adj[i * NNODE + j] + adj2[i * NNODE + j];
            float b = adj[j * NNODE + i] + adj2[j * NNODE + i];
            g_Asym[t] = 0.5f * (a + b);
        }
    }
}

// -------- main fused kernel --------
__global__ void __launch_bounds__(NTHR, 1)
mgc9(const float* __restrict__ x, const float* __restrict__ Mm,
     const float* __restrict__ bias, float* __restrict__ out) {
    extern __shared__ char smem[];
    const uint32_t sb = smem_u32(smem);
    const int tid  = threadIdx.x;
    const int lane = tid & 31;
    const int warp = tid >> 5;
    const int gid  = lane >> 2;
    const int tig  = lane & 3;
    const int wm   = warp % 3;       // M tile: rows wm*48 .. +47
    const int wn   = warp / 3;       // N tile: cols wn*32 .. +31 (of 256)
    const int row0 = blockIdx.x * BM;
    const int d0   = blockIdx.y * 128;

    float* MST = (float*)(smem + MST_OFF);   // MST[c*17+j] = M[j][d0+c]
    float* As  = (float*)(smem + AS_OFF);
    float* bs  = (float*)(smem + BS_OFF);
    float* gs  = (float*)(smem + GS_OFF);    // [144][264]; cols 0..127 g0, 128..255 g1

    for (int e = tid; e < 128 * NNODE; e += NTHR) {
        int c = e / NNODE, j = e % NNODE;
        MST[e] = __ldg(&Mm[j * COUT + d0 + c]);
    }
    for (int e = tid; e < NNODE * NNODE; e += NTHR) As[e] = g_Asym[e];
    for (int e = tid; e < 128; e += NTHR) bs[e] = __ldg(&bias[d0 + e]);
    // zero A pad rows (136..143) in all stages
    for (int e = tid; e < NSTAGE * 8 * LDT; e += NTHR) {
        int buf = e / (8 * LDT), w = e % (8 * LDT);
        *((float*)(smem + A_OFF + buf * A_TILE) + BM * LDT + w) = 0.f;
    }

    float acc[3][4][4];
#pragma unroll
    for (int i = 0; i < 3; i++)
#pragma unroll
        for (int j = 0; j < 4; j++)
#pragma unroll
            for (int q = 0; q < 4; q++) acc[i][j][q] = 0.f;

    // ---- cp.async chunk fill ----
    auto fill = [&](int kt, int buf) {
        const int k0 = kt * KC;
        const uint32_t ab = sb + A_OFF + buf * A_TILE;
        for (int e = tid; e < BM * 8; e += NTHR) {
            int r = e >> 3, c = e & 7;
            CP16(ab + r * (LDT * 4) + c * 16,
                 x + (size_t)(row0 + r) * CIN + k0 + c * 4);
        }
        const uint32_t bb = sb + B_OFF + buf * B_TILE;
        for (int e = tid; e < 256 * 8; e += NTHR) {
            int n = e >> 3, c = e & 7;
            int gn = d0 + n + (n & 128);   // n<128 -> W0 col d0+n ; n>=128 -> W1 col d0+n-128
            CP16(bb + n * (LDT * 4) + c * 16, g_Wt + gn * 256 + k0 + c * 4);
        }
        asm volatile("cp.async.commit_group;" ::: "memory");
    };

    // ldmatrix per-lane offset: row = (lane&15), 16B half = (lane>>4)
    const uint32_t frag_off = (uint32_t)(lane & 15) * (LDT * 4) + (uint32_t)(lane >> 4) * 16;
    const uint32_t a_warp_off = (uint32_t)(wm * 48) * (LDT * 4) + frag_off;
    const uint32_t b_warp_off = (uint32_t)(wn * 32) * (LDT * 4) + frag_off;

    auto do_mma = [&](int buf) {
        const uint32_t aaddr = sb + A_OFF + buf * A_TILE + a_warp_off;
        const uint32_t baddr = sb + B_OFF + buf * B_TILE + b_warp_off;
#pragma unroll
        for (int s = 0; s < 4; s++) {
            const uint32_t koff = s * 32;          // 8 tf32 * 4B
            uint32_t a[3][4], bq[2][4];
            // first MMA needs a[0] and bq[0]: issue them earliest
            LDSM4(a[0], aaddr + koff);
            LDSM4(bq[0], baddr + koff);
            LDSM4(bq[1], baddr + 16 * (LDT * 4) + koff);
            LDSM4(a[1], aaddr + 16 * (LDT * 4) + koff);
            LDSM4(a[2], aaddr + 32 * (LDT * 4) + koff);
#pragma unroll
            for (int mt = 0; mt < 3; mt++)
#pragma unroll
                for (int nf = 0; nf < 4; nf++)
                    MMA_TF32(acc[mt][nf], a[mt],
                             bq[nf >> 1][nf & 1], bq[nf >> 1][2 + (nf & 1)]);
        }
    };

    // ---- pipeline: 3-stage cp.async, ONE sync per chunk ----
    fill(0, 0);
    fill(1, 1);
    for (int t = 0; t < NCHUNK; t++) {
        if (t < NCHUNK - 1) asm volatile("cp.async.wait_group 1;" ::: "memory");
        else                asm volatile("cp.async.wait_group 0;" ::: "memory");
        __syncthreads();                       // chunk t ready; all done with t-1
        if (t + 2 < NCHUNK) fill(t + 2, (t + 2) % NSTAGE);   // overwrites slot of t-1
        do_mma(t % NSTAGE);
    }
    __syncthreads();   // all warps done reading tiles before gs overlay

    // ---- epilogue: g = M * H into gs ----
#pragma unroll
    for (int mt = 0; mt < 3; mt++) {
        int r0 = wm * 48 + mt * 16 + gid;
        int r1 = r0 + 8;
        int jj0 = r0 % NNODE, jj1 = r1 % NNODE;
#pragma unroll
        for (int nf = 0; nf < 4; nf++) {
            int c0 = wn * 32 + nf * 8 + 2 * tig;
            int cl = c0 & 127;
            float m00 = MST[cl * NNODE + jj0], m01 = MST[(cl + 1) * NNODE + jj0];
            float m10 = MST[cl * NNODE + jj1], m11 = MST[(cl + 1) * NNODE + jj1];
            *(float2*)(gs + r0 * LDGS + c0) =
                make_float2(acc[mt][nf][0] * m00, acc[mt][nf][1] * m01);
            *(float2*)(gs + r1 * LDGS + c0) =
                make_float2(acc[mt][nf][2] * m10, acc[mt][nf][3] * m11);
        }
    }
    __syncthreads();

    // ---- mixing: out[i,d] = sum_j A[i,j]*g1[j,d] + A[i,i]*(g0[i,d]-g1[i,d]) + bias ----
    // 512 threads, float2 granularity: item = batch (8) x dn2 (64)
    if (tid < 512) {
        const int bb2 = tid >> 6, dn2 = tid & 63;
        const int rb = bb2 * NNODE;
        float2 ac[NNODE];
#pragma unroll
        for (int i = 0; i < NNODE; i++) ac[i] = make_float2(0.f, 0.f);
#pragma unroll
        for (int j = 0; j < NNODE; j++) {
            float2 gj = *(const float2*)(gs + (rb + j) * LDGS + 128 + dn2 * 2);
#pragma unroll
            for (int i = 0; i < NNODE; i++) {
                float a = As[i * NNODE + j];
                ac[i].x = fmaf(a, gj.x, ac[i].x);
                ac[i].y = fmaf(a, gj.y, ac[i].y);
            }
        }
        float2 bv = *(const float2*)(bs + dn2 * 2);
#pragma unroll
        for (int i = 0; i < NNODE; i++) {
            int rr = rb + i;
            float2 g0 = *(const float2*)(gs + rr * LDGS + dn2 * 2);
            float2 g1 = *(const float2*)(gs + rr * LDGS + 128 + dn2 * 2);
            float aii = As[i * NNODE + i];
            float2 v;
            v.x = ac[i].x + aii * (g0.x - g1.x) + bv.x;
            v.y = ac[i].y + aii * (g0.y - g1.y) + bv.y;
            *(float2*)(out + (size_t)(row0 + rr) * COUT + d0 + dn2 * 2) = v;
        }
    }
}

extern "C" void kernel_launch(void* const* d_in, const int* in_sizes, int n_in,
                              void* d_out, int out_size) {
    const float* x    = (const float*)d_in[0];
    const float* W    = (const float*)d_in[1];
    const float* Mm   = (const float*)d_in[2];
    const float* adj  = (const float*)d_in[3];
    const float* adj2 = (const float*)d_in[4];
    const float* bias = (const float*)d_in[5];
    float* out = (float*)d_out;
    (void)in_sizes; (void)n_in; (void)out_size;

    cudaFuncSetAttribute(mgc9, cudaFuncAttributeMaxDynamicSharedMemorySize, SMEM_TOTAL);

    mgc_prep<<<512, 256>>>(W, adj, adj2);
    dim3 grid(8192 / TB, 2);
    mgc9<<<grid, NTHR, SMEM_TOTAL>>>(x, Mm, bias, out);
}

// round 17
// speedup vs baseline: 1.0587x; 1.0587x over previous
#include <cuda_runtime.h>
#include <cstdint>

// ---------------- Problem constants ----------------
#define NNODE   17
#define CIN     256
#define COUT    256
#define TB      8
#define BM      136                  // TB * NNODE rows per CTA
#define BMP     144
#define NTHR    384                  // 12 warps: 3 (M) x 4 (N)
#define KC      64                   // K per chunk (doubled: fewer boundaries)
#define NCHUNK  4                    // 256 / 64
#define NSTAGE  2
#define LDT     68                   // tile row stride (floats): 68 mod 32 = 4 -> conflict-free
#define LDGS    264                  // gs row stride (floats)

// ---------------- SMEM layout (bytes) ----------------
#define A_OFF   0
#define A_TILE  (BMP * LDT * 4)             // 39168
#define B_OFF   (NSTAGE * A_TILE)           // 78336
#define B_TILE  (256 * LDT * 4)             // 69632  (tiles end at 217600)
#define GS_OFF  0                           // epilogue overlay [144][264] = 152064
#define MST_OFF 217600                      // M transposed [128 cols][17] = 8704
#define AS_OFF  226304                      // 289 floats (+pad)
#define BS_OFF  227472                      // 128 floats
#define SMEM_TOTAL 227984

__device__ __align__(16) float g_Wt[512 * 256];   // [n][k] tf32-rounded; n = mat*256 + d
__device__ float g_Asym[NNODE * NNODE];

__device__ __forceinline__ uint32_t smem_u32(const void* p) {
    uint32_t a;
    asm("{ .reg .u64 t; cvta.to.shared.u64 t, %1; cvt.u32.u64 %0, t; }" : "=r"(a) : "l"(p));
    return a;
}

#define CP16(dst, src) asm volatile("cp.async.cg.shared.global [%0], [%1], 16;" \
    :: "r"(dst), "l"(__cvta_generic_to_global(src)))

#define LDSM4(r, addr) asm volatile( \
    "ldmatrix.sync.aligned.m8n8.x4.shared.b16 {%0,%1,%2,%3}, [%4];" \
    : "=r"((r)[0]), "=r"((r)[1]), "=r"((r)[2]), "=r"((r)[3]) : "r"(addr))

#define MMA_TF32(c, a, b0, b1) asm volatile( \
    "mma.sync.aligned.m16n8k8.row.col.f32.tf32.tf32.f32 " \
    "{%0,%1,%2,%3}, {%4,%5,%6,%7}, {%8,%9}, {%0,%1,%2,%3};" \
    : "+f"((c)[0]), "+f"((c)[1]), "+f"((c)[2]), "+f"((c)[3]) \
    : "r"((a)[0]), "r"((a)[1]), "r"((a)[2]), "r"((a)[3]), "r"(b0), "r"(b1))

__device__ __forceinline__ uint32_t to_tf32(float f) {
    unsigned u; asm("cvt.rna.tf32.f32 %0, %1;" : "=r"(u) : "f"(f));
    return u;
}

// -------- prep: W -> [n][k] transposed + tf32-rounded; symmetrize A --------
__global__ void mgc_prep(const float* __restrict__ W, const float* __restrict__ adj,
                         const float* __restrict__ adj2) {
    int e = blockIdx.x * 256 + threadIdx.x;
    if (e < 512 * 256) {
        int n = e >> 8, k = e & 255;
        int mat = n >> 8, d = n & 255;
        g_Wt[e] = __uint_as_float(to_tf32(W[mat * (CIN * COUT) + k * COUT + d]));
    }
    if (blockIdx.x == 0) {
        for (int t = threadIdx.x; t < NNODE * NNODE; t += 256) {
            int i = t / NNODE, j = t % NNODE;
            float a = adj[i * NNODE + j] + adj2[i * NNODE + j];
            float b = adj[j * NNODE + i] + adj2[j * NNODE + i];
            g_Asym[t] = 0.5f * (a + b);
        }
    }
}

// -------- main fused kernel --------
__global__ void __launch_bounds__(NTHR, 1)
mgc10(const float* __restrict__ x, const float* __restrict__ Mm,
      const float* __restrict__ bias, float* __restrict__ out) {
    extern __shared__ char smem[];
    const uint32_t sb = smem_u32(smem);
    const int tid  = threadIdx.x;
    const int lane = tid & 31;
    const int warp = tid >> 5;
    const int gid  = lane >> 2;
    const int tig  = lane & 3;
    const int wm   = warp % 3;       // M tile: rows wm*48 .. +47
    const int wn   = warp / 3;       // N tile: cols wn*64 .. +63 (of 256)
    const int row0 = blockIdx.x * BM;
    const int d0   = blockIdx.y * 128;

    float* MST = (float*)(smem + MST_OFF);   // MST[c*17+j] = M[j][d0+c]
    float* As  = (float*)(smem + AS_OFF);
    float* bs  = (float*)(smem + BS_OFF);
    float* gs  = (float*)(smem + GS_OFF);    // [144][264]; cols 0..127 g0, 128..255 g1

    for (int e = tid; e < 128 * NNODE; e += NTHR) {
        int c = e / NNODE, j = e % NNODE;
        MST[e] = __ldg(&Mm[j * COUT + d0 + c]);
    }
    for (int e = tid; e < NNODE * NNODE; e += NTHR) As[e] = g_Asym[e];
    for (int e = tid; e < 128; e += NTHR) bs[e] = __ldg(&bias[d0 + e]);
    // zero A pad rows (136..143) in both stages
    for (int e = tid; e < NSTAGE * 8 * LDT; e += NTHR) {
        int buf = e / (8 * LDT), w = e % (8 * LDT);
        *((float*)(smem + A_OFF + buf * A_TILE) + BM * LDT + w) = 0.f;
    }

    float acc[3][8][4];
#pragma unroll
    for (int i = 0; i < 3; i++)
#pragma unroll
        for (int j = 0; j < 8; j++)
#pragma unroll
            for (int q = 0; q < 4; q++) acc[i][j][q] = 0.f;

    // ---- cp.async chunk fill (64 floats = 16 CP16 per row) ----
    auto fill = [&](int kt, int buf) {
        const int k0 = kt * KC;
        const uint32_t ab = sb + A_OFF + buf * A_TILE;
        for (int e = tid; e < BM * 16; e += NTHR) {
            int r = e >> 4, c = e & 15;
            CP16(ab + r * (LDT * 4) + c * 16,
                 x + (size_t)(row0 + r) * CIN + k0 + c * 4);
        }
        const uint32_t bb = sb + B_OFF + buf * B_TILE;
        for (int e = tid; e < 256 * 16; e += NTHR) {
            int n = e >> 4, c = e & 15;
            int gn = d0 + n + (n & 128);   // n<128 -> W0 col d0+n ; n>=128 -> W1 col d0+n-128
            CP16(bb + n * (LDT * 4) + c * 16, g_Wt + gn * 256 + k0 + c * 4);
        }
        asm volatile("cp.async.commit_group;" ::: "memory");
    };

    // ldmatrix per-lane offset: row = (lane&15), 16B half = (lane>>4)
    const uint32_t frag_off = (uint32_t)(lane & 15) * (LDT * 4) + (uint32_t)(lane >> 4) * 16;
    const uint32_t a_warp_off = (uint32_t)(wm * 48) * (LDT * 4) + frag_off;
    const uint32_t b_warp_off = (uint32_t)(wn * 64) * (LDT * 4) + frag_off;

    auto do_mma = [&](int buf) {
        const uint32_t aaddr = sb + A_OFF + buf * A_TILE + a_warp_off;
        const uint32_t baddr = sb + B_OFF + buf * B_TILE + b_warp_off;
#pragma unroll
        for (int s = 0; s < 8; s++) {
            const uint32_t koff = s * 32;          // 8 tf32 * 4B
            uint32_t a[3][4], bq[4][4];
            LDSM4(a[0], aaddr + koff);
#pragma unroll
            for (int np = 0; np < 4; np++)
                LDSM4(bq[np], baddr + np * 16 * (LDT * 4) + koff);
            LDSM4(a[1], aaddr + 16 * (LDT * 4) + koff);
            LDSM4(a[2], aaddr + 32 * (LDT * 4) + koff);
#pragma unroll
            for (int mt = 0; mt < 3; mt++)
#pragma unroll
                for (int nf = 0; nf < 8; nf++)
                    MMA_TF32(acc[mt][nf], a[mt],
                             bq[nf >> 1][nf & 1], bq[nf >> 1][2 + (nf & 1)]);
        }
    };

    // ---- pipeline: 2-stage, 4 chunks ----
    fill(0, 0);
    fill(1, 1);
    for (int t = 0; t < NCHUNK; t++) {
        if (t < NCHUNK - 1) asm volatile("cp.async.wait_group 1;" ::: "memory");
        else                asm volatile("cp.async.wait_group 0;" ::: "memory");
        __syncthreads();                     // chunk t landed
        do_mma(t & 1);
        __syncthreads();                     // all warps done reading stage t&1
        if (t + 2 < NCHUNK) fill(t + 2, t & 1);
    }

    // ---- epilogue: g = M * H into gs ----
#pragma unroll
    for (int mt = 0; mt < 3; mt++) {
        int r0 = wm * 48 + mt * 16 + gid;
        int r1 = r0 + 8;
        int jj0 = r0 % NNODE, jj1 = r1 % NNODE;
#pragma unroll
        for (int nf = 0; nf < 8; nf++) {
            int c0 = wn * 64 + nf * 8 + 2 * tig;
            int cl = c0 & 127;
            float m00 = MST[cl * NNODE + jj0], m01 = MST[(cl + 1) * NNODE + jj0];
            float m10 = MST[cl * NNODE + jj1], m11 = MST[(cl + 1) * NNODE + jj1];
            *(float2*)(gs + r0 * LDGS + c0) =
                make_float2(acc[mt][nf][0] * m00, acc[mt][nf][1] * m01);
            *(float2*)(gs + r1 * LDGS + c0) =
                make_float2(acc[mt][nf][2] * m10, acc[mt][nf][3] * m11);
        }
    }
    __syncthreads();

    // ---- mixing: out[i,d] = sum_j A[i,j]*g1[j,d] + A[i,i]*(g0[i,d]-g1[i,d]) + bias ----
    if (tid < TB * 32) {
        const int bb2 = tid >> 5, dn4 = tid & 31;
        const int rb = bb2 * NNODE;
        float4 ac[NNODE];
#pragma unroll
        for (int i = 0; i < NNODE; i++) ac[i] = make_float4(0.f, 0.f, 0.f, 0.f);
#pragma unroll
        for (int j = 0; j < NNODE; j++) {
            float4 gj = *(const float4*)(gs + (rb + j) * LDGS + 128 + dn4 * 4);
#pragma unroll
            for (int i = 0; i < NNODE; i++) {
                float a = As[i * NNODE + j];
                ac[i].x = fmaf(a, gj.x, ac[i].x);
                ac[i].y = fmaf(a, gj.y, ac[i].y);
                ac[i].z = fmaf(a, gj.z, ac[i].z);
                ac[i].w = fmaf(a, gj.w, ac[i].w);
            }
        }
        float4 bv = *(const float4*)(bs + dn4 * 4);
#pragma unroll
        for (int i = 0; i < NNODE; i++) {
            int rr = rb + i;
            float4 g0 = *(const float4*)(gs + rr * LDGS + dn4 * 4);
            float4 g1 = *(const float4*)(gs + rr * LDGS + 128 + dn4 * 4);
            float aii = As[i * NNODE + i];
            float4 v;
            v.x = ac[i].x + aii * (g0.x - g1.x) + bv.x;
            v.y = ac[i].y + aii * (g0.y - g1.y) + bv.y;
            v.z = ac[i].z + aii * (g0.z - g1.z) + bv.z;
            v.w = ac[i].w + aii * (g0.w - g1.w) + bv.w;
            *(float4*)(out + (size_t)(row0 + rr) * COUT + d0 + dn4 * 4) = v;
        }
    }
}

extern "C" void kernel_launch(void* const* d_in, const int* in_sizes, int n_in,
                              void* d_out, int out_size) {
    const float* x    = (const float*)d_in[0];
    const float* W    = (const float*)d_in[1];
    const float* Mm   = (const float*)d_in[2];
    const float* adj  = (const float*)d_in[3];
    const float* adj2 = (const float*)d_in[4];
    const float* bias = (const float*)d_in[5];
    float* out = (float*)d_out;
    (void)in_sizes; (void)n_in; (void)out_size;

    cudaFuncSetAttribute(mgc10, cudaFuncAttributeMaxDynamicSharedMemorySize, SMEM_TOTAL);

    mgc_prep<<<512, 256>>>(W, adj, adj2);
    dim3 grid(8192 / TB, 2);
    mgc10<<<grid, NTHR, SMEM_TOTAL>>>(x, Mm, bias, out);
}